// round 1
// baseline (speedup 1.0000x reference)
#include <cuda_runtime.h>
#include <math.h>

#define BB 2
#define NN 512
#define SS 384
#define ZC 128
#define HH 12
#define CC 16
#define PQn 4
#define PVn 8
#define HC 192      /* H*C   */
#define HPQ3 144    /* H*PQ*3*/
#define HPV3 288    /* H*PV*3*/
#define CATW 2112   /* H*(C+4PV+Z) */
#define PROJ_W 1152

#define WLC  0.5773502691896258f     /* sqrt(1/3) */
#define COEF 0.06804138174397717f    /* wL*wC/2, wC=sqrt(2/(9*PQ)) */

__device__ __align__(16) float g_q [BB*NN*HC];
__device__ __align__(16) float g_k [BB*NN*HC];
__device__ __align__(16) float g_v [BB*NN*HC];
__device__ __align__(16) float g_qp[BB*NN*HPQ3];
__device__ __align__(16) float g_kp[BB*NN*HPQ3];
__device__ __align__(16) float g_vp[BB*NN*HPV3];
__device__ __align__(16) float g_qq[BB*NN*HH];
__device__ __align__(16) float g_kk[BB*NN*HH];
__device__ __align__(16) float g_cat[BB*NN*CATW];

__device__ __forceinline__ float dot4(float4 a, float4 b) {
    return a.x*b.x + a.y*b.y + a.z*b.z + a.w*b.w;
}

// ---------------------------------------------------------------------------
// Kernel 1: projections + frame transform. One block per (b,n) residue.
// ---------------------------------------------------------------------------
__global__ __launch_bounds__(256) void k_proj(
    const float* __restrict__ s, const float* __restrict__ R, const float* __restrict__ t,
    const float* __restrict__ Wq, const float* __restrict__ Wk, const float* __restrict__ Wv,
    const float* __restrict__ Wqp, const float* __restrict__ Wkp, const float* __restrict__ Wvp)
{
    __shared__ float s_sh[SS];
    __shared__ __align__(16) float proj[PROJ_W];
    __shared__ float qq_sh[HH], kk_sh[HH];
    __shared__ float Rl[9], tl[3];
    const int bn  = blockIdx.x;
    const int tid = threadIdx.x;

    for (int i = tid; i < SS; i += 256) s_sh[i] = s[bn*SS + i];
    if (tid < HH) { qq_sh[tid] = 0.f; kk_sh[tid] = 0.f; }
    if (tid < 9)  Rl[tid] = R[bn*9 + tid];
    if (tid < 3)  tl[tid] = t[bn*3 + tid];
    __syncthreads();

    // 288 float4 output groups over the concatenated 1152-wide projection
    for (int g = tid; g < PROJ_W/4; g += 256) {
        const int o4 = g*4;
        const float* W; int OD, o;
        if      (o4 < 192) { W = Wq;  OD = 192; o = o4;       }
        else if (o4 < 384) { W = Wk;  OD = 192; o = o4 - 192; }
        else if (o4 < 576) { W = Wv;  OD = 192; o = o4 - 384; }
        else if (o4 < 720) { W = Wqp; OD = 144; o = o4 - 576; }
        else if (o4 < 864) { W = Wkp; OD = 144; o = o4 - 720; }
        else               { W = Wvp; OD = 288; o = o4 - 864; }
        float4 acc = make_float4(0.f, 0.f, 0.f, 0.f);
        const float* Wp = W + o;
        #pragma unroll 4
        for (int si = 0; si < SS; si++) {
            const float  sv = s_sh[si];
            const float4 wv = *(const float4*)(Wp + si*OD);
            acc.x += sv*wv.x; acc.y += sv*wv.y; acc.z += sv*wv.z; acc.w += sv*wv.w;
        }
        *(float4*)(proj + o4) = acc;
    }
    __syncthreads();

    for (int i = tid; i < HC; i += 256) {
        g_q[bn*HC + i] = proj[i];
        g_k[bn*HC + i] = proj[192 + i];
        g_v[bn*HC + i] = proj[384 + i];
    }
    // qp / kp -> global frame + per-head squared norms
    for (int w = tid; w < 96; w += 256) {
        const int which = w / 48;       // 0: qp, 1: kp
        const int pt    = w % 48;       // h*PQ + p
        const int off   = which ? 720 : 576;
        const float px = proj[off + pt*3], py = proj[off + pt*3 + 1], pz = proj[off + pt*3 + 2];
        const float gx = Rl[0]*px + Rl[1]*py + Rl[2]*pz + tl[0];
        const float gy = Rl[3]*px + Rl[4]*py + Rl[5]*pz + tl[1];
        const float gz = Rl[6]*px + Rl[7]*py + Rl[8]*pz + tl[2];
        float* dst = (which ? g_kp : g_qp) + bn*HPQ3 + pt*3;
        dst[0] = gx; dst[1] = gy; dst[2] = gz;
        atomicAdd((which ? kk_sh : qq_sh) + pt/PQn, gx*gx + gy*gy + gz*gz);
    }
    // vp -> global frame
    for (int pt = tid; pt < 96; pt += 256) {
        const float px = proj[864 + pt*3], py = proj[864 + pt*3 + 1], pz = proj[864 + pt*3 + 2];
        float* dst = g_vp + bn*HPV3 + pt*3;
        dst[0] = Rl[0]*px + Rl[1]*py + Rl[2]*pz + tl[0];
        dst[1] = Rl[3]*px + Rl[4]*py + Rl[5]*pz + tl[1];
        dst[2] = Rl[6]*px + Rl[7]*py + Rl[8]*pz + tl[2];
    }
    __syncthreads();
    if (tid < HH) { g_qq[bn*HH + tid] = qq_sh[tid]; g_kk[bn*HH + tid] = kk_sh[tid]; }
}

// ---------------------------------------------------------------------------
// Kernel 2: fused bias + logits + softmax + (o, opt, norm, opair) -> g_cat.
// One block handles 4 query rows (same batch), 512 threads = one per key j.
// ---------------------------------------------------------------------------
// dyn-smem layout (floats):
#define L_LOGITS 0                 /* 4*12*512 = 24576 */
#define L_WBT    24576             /* 12*128   =  1536 */
#define L_QS     26112             /* 4*192    =   768 */
#define L_QPS    26880             /* 4*192    =   768 */
#define L_QQS    27648             /* 48 */
#define L_GM     27696             /* 12 */
#define L_RS     27708             /* 36 */
#define L_TS     27744             /* 12 */
#define L_OGS    27756             /* 4*288 = 1152 */
#define ATTN_SMEM_FLOATS 28908
#define ATTN_SMEM_BYTES  (ATTN_SMEM_FLOATS*4)

__global__ __launch_bounds__(512) void k_attn(
    const float* __restrict__ z, const float* __restrict__ Wb,
    const float* __restrict__ hw, const float* __restrict__ R,
    const float* __restrict__ t)
{
    extern __shared__ __align__(16) float sm[];
    float* logits = sm + L_LOGITS;
    float* wbT    = sm + L_WBT;
    float* q_s    = sm + L_QS;
    float* qp_s   = sm + L_QPS;
    float* qq_s   = sm + L_QQS;
    float* gm     = sm + L_GM;
    float* R_s    = sm + L_RS;
    float* t_s    = sm + L_TS;
    float* og_s   = sm + L_OGS;

    const int tid = threadIdx.x;
    const int blk = blockIdx.x;
    const int b   = blk >> 7;            // 128 blocks per batch
    const int i0  = (blk & 127) << 2;    // 4 query rows per block

    // ---- setup ----
    for (int idx = tid; idx < HH*ZC; idx += 512) {
        const int h = idx / ZC, zi = idx % ZC;
        wbT[h*ZC + zi] = Wb[zi*HH + h];
    }
    for (int idx = tid; idx < 4*HC; idx += 512) {
        const int il = idx / HC;
        q_s[idx] = g_q[(b*NN + i0 + il)*HC + (idx % HC)];
    }
    for (int idx = tid; idx < 4*HPQ3; idx += 512) {
        const int il = idx / HPQ3, r = idx % HPQ3;
        const int h = r / 12, d = r % 12;
        qp_s[il*192 + h*16 + d] = g_qp[(b*NN + i0 + il)*HPQ3 + r];
    }
    if (tid < 48) qq_s[tid] = g_qq[(b*NN + i0 + tid/12)*HH + tid%12];
    if (tid < HH) gm[tid]   = log1pf(expf(hw[tid]));          // softplus
    if (tid < 36) R_s[tid]  = R[(b*NN + i0 + tid/9)*9 + tid%9];
    if (tid < 12) t_s[tid]  = t[(b*NN + i0 + tid/3)*3 + tid%3];
    __syncthreads();

    const int j = tid;   // this thread's key index

    // ---- phase 1a: pair bias (z @ Wb), all 12 heads per thread ----
    for (int il = 0; il < 4; il++) {
        float acc[HH];
        #pragma unroll
        for (int h = 0; h < HH; h++) acc[h] = 0.f;
        const float4* zr = (const float4*)(z + ((b*NN + i0 + il)*NN + j)*ZC);
        #pragma unroll 4
        for (int c4 = 0; c4 < ZC/4; c4++) {
            const float4 zv = zr[c4];
            #pragma unroll
            for (int h = 0; h < HH; h++) {
                const float4 wv = *(const float4*)(wbT + h*ZC + c4*4);
                acc[h] += zv.x*wv.x + zv.y*wv.y + zv.z*wv.z + zv.w*wv.w;
            }
        }
        #pragma unroll
        for (int h = 0; h < HH; h++) logits[(il*HH + h)*NN + j] = acc[h];
    }

    // ---- phase 1b: scalar + point logits ----
    {
        const float4* kr  = (const float4*)(g_k  + (b*NN + j)*HC);
        const float4* kpr = (const float4*)(g_kp + (b*NN + j)*HPQ3);
        const float*  kkr = g_kk + (b*NN + j)*HH;
        for (int h = 0; h < HH; h++) {
            const float4 kv0 = kr[h*4+0], kv1 = kr[h*4+1], kv2 = kr[h*4+2], kv3 = kr[h*4+3];
            const float4 kp0 = kpr[h*3+0], kp1 = kpr[h*3+1], kp2 = kpr[h*3+2];
            const float  kkh = kkr[h];
            const float  gch = COEF * gm[h];
            #pragma unroll
            for (int il = 0; il < 4; il++) {
                const float4* qh  = (const float4*)(q_s  + il*192 + h*16);
                const float4* qph = (const float4*)(qp_s + il*192 + h*16);
                float sc = dot4(qh[0],kv0) + dot4(qh[1],kv1) + dot4(qh[2],kv2) + dot4(qh[3],kv3);
                float qk = dot4(qph[0],kp0) + dot4(qph[1],kp1) + dot4(qph[2],kp2);
                const float d2 = qq_s[il*HH + h] + kkh - 2.f*qk;
                const int   li = (il*HH + h)*NN + j;
                logits[li] = WLC*(sc*0.25f + logits[li]) - gch*d2;
            }
        }
    }
    __syncthreads();

    // ---- phase 2: softmax over j, one warp per (il,h) row ----
    {
        const int wid = tid >> 5, lane = tid & 31;
        for (int row = wid; row < 48; row += 16) {
            float* Lr = logits + row*NN;
            float m = -1e30f;
            for (int c = lane; c < NN; c += 32) m = fmaxf(m, Lr[c]);
            #pragma unroll
            for (int o = 16; o; o >>= 1) m = fmaxf(m, __shfl_xor_sync(0xffffffffu, m, o));
            float ssum = 0.f;
            for (int c = lane; c < NN; c += 32) { const float e = __expf(Lr[c] - m); Lr[c] = e; ssum += e; }
            #pragma unroll
            for (int o = 16; o; o >>= 1) ssum += __shfl_xor_sync(0xffffffffu, ssum, o);
            const float inv = 1.f / ssum;
            for (int c = lane; c < NN; c += 32) Lr[c] *= inv;
        }
    }
    __syncthreads();

    // ---- phase 3a: opair = a @ z  (thread = (il, z-col), 12 heads in regs) ----
    {
        const int il  = tid >> 7;
        const int col = tid & 127;
        float acc[HH];
        #pragma unroll
        for (int h = 0; h < HH; h++) acc[h] = 0.f;
        const float* zcol = z + (b*NN + i0 + il)*NN*ZC + col;
        const float* arow = logits + il*HH*NN;
        for (int jj = 0; jj < NN; jj++) {
            const float zv = zcol[jj*ZC];
            #pragma unroll
            for (int h = 0; h < HH; h++) acc[h] += arow[h*NN + jj] * zv;
        }
        float* dst = g_cat + (b*NN + i0 + il)*CATW + 576 + col;
        #pragma unroll
        for (int h = 0; h < HH; h++) dst[h*ZC] = acc[h];
    }

    // ---- phase 3b: o = a @ v ----
    for (int idx = tid; idx < 4*HC; idx += 512) {
        const int il = idx / HC, hc = idx % HC, h = hc >> 4;
        const float* arow = logits + (il*HH + h)*NN;
        const float* vcol = g_v + b*NN*HC + hc;
        float a0 = 0.f, a1 = 0.f, a2 = 0.f, a3 = 0.f;
        for (int jj = 0; jj < NN; jj += 4) {
            a0 += arow[jj+0]*vcol[(jj+0)*HC];
            a1 += arow[jj+1]*vcol[(jj+1)*HC];
            a2 += arow[jj+2]*vcol[(jj+2)*HC];
            a3 += arow[jj+3]*vcol[(jj+3)*HC];
        }
        g_cat[(b*NN + i0 + il)*CATW + hc] = (a0+a1)+(a2+a3);
    }

    // ---- phase 3c: opt_global = a @ vp ----
    for (int idx = tid; idx < 4*HPV3; idx += 512) {
        const int il = idx / HPV3, d = idx % HPV3, h = d / 24;
        const float* arow = logits + (il*HH + h)*NN;
        const float* vcol = g_vp + b*NN*HPV3 + d;
        float a0 = 0.f, a1 = 0.f, a2 = 0.f, a3 = 0.f;
        for (int jj = 0; jj < NN; jj += 4) {
            a0 += arow[jj+0]*vcol[(jj+0)*HPV3];
            a1 += arow[jj+1]*vcol[(jj+1)*HPV3];
            a2 += arow[jj+2]*vcol[(jj+2)*HPV3];
            a3 += arow[jj+3]*vcol[(jj+3)*HPV3];
        }
        og_s[il*HPV3 + d] = (a0+a1)+(a2+a3);
    }
    __syncthreads();

    // ---- phase 3d: back to local frame (R^T (x - t)), + norms ----
    for (int idx = tid; idx < 4*96; idx += 512) {
        const int il = idx / 96, hp = idx % 96;  // hp = h*8 + p
        const float dx = og_s[il*HPV3 + hp*3 + 0] - t_s[il*3 + 0];
        const float dy = og_s[il*HPV3 + hp*3 + 1] - t_s[il*3 + 1];
        const float dz = og_s[il*HPV3 + hp*3 + 2] - t_s[il*3 + 2];
        const float* Rr = R_s + il*9;
        const float ox = Rr[0]*dx + Rr[3]*dy + Rr[6]*dz;
        const float oy = Rr[1]*dx + Rr[4]*dy + Rr[7]*dz;
        const float oz = Rr[2]*dx + Rr[5]*dy + Rr[8]*dz;
        float* cg = g_cat + (b*NN + i0 + il)*CATW;
        cg[192 + hp*3 + 0] = ox;
        cg[192 + hp*3 + 1] = oy;
        cg[192 + hp*3 + 2] = oz;
        cg[480 + hp] = sqrtf(ox*ox + oy*oy + oz*oz + 1e-8f);
    }
}

// ---------------------------------------------------------------------------
// Kernel 3: out = g_cat[1024,2112] @ Wout[2112,384]. 32x64 tile, 128 threads.
// ---------------------------------------------------------------------------
__global__ __launch_bounds__(128) void k_out(const float* __restrict__ Wout,
                                             float* __restrict__ out)
{
    __shared__ __align__(16) float As[32][36];
    __shared__ __align__(16) float Bs[32][64];
    const int bm = blockIdx.y, bn = blockIdx.x;
    const int tid = threadIdx.x;
    const int ty = tid >> 4, tx = tid & 15;
    float acc[4][4];
    #pragma unroll
    for (int i = 0; i < 4; i++)
        #pragma unroll
        for (int jj = 0; jj < 4; jj++) acc[i][jj] = 0.f;

    const float* Arow = g_cat + bm*32*CATW;
    for (int kt = 0; kt < CATW/32; kt++) {
        const int k0 = kt*32;
        #pragma unroll
        for (int r = 0; r < 8; r++) {
            const int idx = tid + r*128;
            const int m = idx >> 5, kk = idx & 31;
            As[kk][m] = Arow[m*CATW + k0 + kk];
        }
        #pragma unroll
        for (int r = 0; r < 16; r++) {
            const int idx = tid + r*128;
            const int kk = idx >> 6, n = idx & 63;
            Bs[kk][n] = Wout[(k0 + kk)*SS + bn*64 + n];
        }
        __syncthreads();
        #pragma unroll
        for (int kk = 0; kk < 32; kk++) {
            const float4 av = *(const float4*)&As[kk][ty*4];
            const float4 bv = *(const float4*)&Bs[kk][tx*4];
            acc[0][0] += av.x*bv.x; acc[0][1] += av.x*bv.y; acc[0][2] += av.x*bv.z; acc[0][3] += av.x*bv.w;
            acc[1][0] += av.y*bv.x; acc[1][1] += av.y*bv.y; acc[1][2] += av.y*bv.z; acc[1][3] += av.y*bv.w;
            acc[2][0] += av.z*bv.x; acc[2][1] += av.z*bv.y; acc[2][2] += av.z*bv.z; acc[2][3] += av.z*bv.w;
            acc[3][0] += av.w*bv.x; acc[3][1] += av.w*bv.y; acc[3][2] += av.w*bv.z; acc[3][3] += av.w*bv.w;
        }
        __syncthreads();
    }
    #pragma unroll
    for (int i = 0; i < 4; i++) {
        float4 v = make_float4(acc[i][0], acc[i][1], acc[i][2], acc[i][3]);
        *(float4*)&out[(bm*32 + ty*4 + i)*SS + bn*64 + tx*4] = v;
    }
}

// ---------------------------------------------------------------------------
extern "C" void kernel_launch(void* const* d_in, const int* in_sizes, int n_in,
                              void* d_out, int out_size)
{
    const float* s    = (const float*)d_in[0];
    const float* z    = (const float*)d_in[1];
    const float* R    = (const float*)d_in[2];
    const float* t    = (const float*)d_in[3];
    const float* Wq   = (const float*)d_in[4];
    const float* Wk   = (const float*)d_in[5];
    const float* Wv   = (const float*)d_in[6];
    const float* Wqp  = (const float*)d_in[7];
    const float* Wkp  = (const float*)d_in[8];
    const float* Wvp  = (const float*)d_in[9];
    const float* Wb   = (const float*)d_in[10];
    const float* hw   = (const float*)d_in[11];
    const float* Wout = (const float*)d_in[12];
    float* out = (float*)d_out;

    cudaFuncSetAttribute(k_attn, cudaFuncAttributeMaxDynamicSharedMemorySize, ATTN_SMEM_BYTES);

    k_proj<<<BB*NN, 256>>>(s, R, t, Wq, Wk, Wv, Wqp, Wkp, Wvp);
    k_attn<<<BB*(NN/4), 512, ATTN_SMEM_BYTES>>>(z, Wb, hw, R, t);
    dim3 g(SS/64, (BB*NN)/32);
    k_out<<<g, 128>>>(Wout, out);
}